// round 5
// baseline (speedup 1.0000x reference)
#include <cuda_runtime.h>
#include <cstdint>

// Problem constants
#define L_DIM   32
#define BEAM    8
#define KV2     2
#define HEADS   8
#define SEQ     1024
#define HDIM    64
#define VOCAB   50257
#define HIST    128
#define TOPK    8

#define KV_ELEMS      268435456ULL     // 32*8*2*8*1024*64
#define SLAB_F4_SHIFT 18               // 262,144 float4 per (layer,beam) slab

#define BLKS_PER_ROW  16
#define N_BLOCKS      (BEAM * BLKS_PER_ROW)       // 128
#define BLOCK_ELEMS   3142                        // 16*3142 = 50272 >= 50257

#define NEG_INF (__int_as_float(0xff800000))
#define IDX_MAX 0x7fffffff

// cross-kernel / cross-block scratch
__device__ float g_blk_s[BEAM][BLKS_PER_ROW];                 // partial sum(exp)
__device__ float g_blk_topv[BEAM][BLKS_PER_ROW][TOPK];
__device__ int   g_blk_topi[BEAM][BLKS_PER_ROW][TOPK];
__device__ int   g_beam_index[BEAM];
__device__ int   g_ctr = 0;

// sorted-descending insert, all static indices (registers only)
__device__ __forceinline__ void top8_insert(float v, int idx, float lv[TOPK], int li[TOPK])
{
    if (v > lv[TOPK - 1] || (v == lv[TOPK - 1] && idx < li[TOPK - 1])) {
        float cv = v; int ci = idx;
#pragma unroll
        for (int j = 0; j < TOPK; j++) {
            bool gt = (cv > lv[j]) || (cv == lv[j] && ci < li[j]);
            float tv = lv[j]; int ti = li[j];
            if (gt) { lv[j] = cv; li[j] = ci; cv = tv; ci = ti; }
        }
    }
}

// full-warp argmax-remove over per-lane sorted lists -> 8 winners
// (desc, tie: smaller index). All lanes converge; lane 0 stores.
__device__ __forceinline__ void warp_top8_merge(float lv[TOPK], int li[TOPK],
                                                float* out_v, int* out_i)
{
    const unsigned F = 0xffffffffu;
    const int lane = threadIdx.x & 31;
    int ptr = 0;
#pragma unroll
    for (int r = 0; r < TOPK; r++) {
        float rv = NEG_INF; int ri = IDX_MAX;
#pragma unroll
        for (int j = 0; j < TOPK; j++)
            if (j == ptr) { rv = lv[j]; ri = li[j]; }
        int rl = lane;
        for (int off = 16; off; off >>= 1) {
            float ov = __shfl_xor_sync(F, rv, off);
            int   oi = __shfl_xor_sync(F, ri, off);
            int   ol = __shfl_xor_sync(F, rl, off);
            if (ov > rv || (ov == rv && oi < ri)) { rv = ov; ri = oi; rl = ol; }
        }
        if (lane == rl) ptr++;
        if (lane == 0) { out_v[r] = rv; out_i[r] = ri; }
    }
}

// ---------------------------------------------------------------------------
// Kernel 1: partial exp-sum + partial top-8 per (row, block); the LAST block
// to finish performs the cross-block merge, beam selection, and writes all
// small outputs (threadfence + ticket pattern; counter reset for graph replay).
// grid = 128, block = 256.
// ---------------------------------------------------------------------------
__global__ void __launch_bounds__(256) k_partial(const float* __restrict__ logits,
                                                 const float* __restrict__ prev,
                                                 const int*   __restrict__ save_id,
                                                 float*       __restrict__ out)
{
    const int row = blockIdx.x >> 4;      // 0..7
    const int blk = blockIdx.x & 15;      // 0..15
    const int t   = threadIdx.x;
    const int wid = t >> 5, lane = t & 31;
    const unsigned F = 0xffffffffu;
    const float* __restrict__ x = logits + (size_t)row * VOCAB;

    const int base = blk * BLOCK_ELEMS;
    const int end  = min(base + BLOCK_ELEMS, VOCAB);

    // direct exp-sum (logits ~ N(0,1): no overflow risk), 4 independent accums
    float s0 = 0.f, s1 = 0.f, s2 = 0.f, s3 = 0.f;
    float lv[TOPK]; int li[TOPK];
#pragma unroll
    for (int j = 0; j < TOPK; j++) { lv[j] = NEG_INF; li[j] = IDX_MAX; }

#pragma unroll 1
    for (int i = base + t; i < end; i += 1024) {
        const int i1 = i + 256, i2 = i + 512, i3 = i + 768;
        float v0 = x[i];
        s0 += __expf(v0);
        top8_insert(v0, i, lv, li);
        if (i1 < end) { float v = x[i1]; s1 += __expf(v); top8_insert(v, i1, lv, li); }
        if (i2 < end) { float v = x[i2]; s2 += __expf(v); top8_insert(v, i2, lv, li); }
        if (i3 < end) { float v = x[i3]; s3 += __expf(v); top8_insert(v, i3, lv, li); }
    }

    float s = (s0 + s1) + (s2 + s3);
    for (int off = 16; off; off >>= 1)
        s += __shfl_xor_sync(F, s, off);

    __shared__ float sm_s[8];
    __shared__ float s_wv[8][TOPK];
    __shared__ int   s_wi[8][TOPK];
    if (lane == 0) sm_s[wid] = s;
    warp_top8_merge(lv, li, s_wv[wid], s_wi[wid]);
    __syncthreads();

    // warp 0: merge 8 warps x 8 -> block top-8; sum warp partials
    if (wid == 0) {
        float l2[TOPK]; int i2_[TOPK];
        const int f0 = lane, f1 = lane + 32;
        float a = s_wv[f0 >> 3][f0 & 7]; int ai = s_wi[f0 >> 3][f0 & 7];
        float b = s_wv[f1 >> 3][f1 & 7]; int bi = s_wi[f1 >> 3][f1 & 7];
        if (b > a || (b == a && bi < ai)) { l2[0] = b; i2_[0] = bi; l2[1] = a; i2_[1] = ai; }
        else                              { l2[0] = a; i2_[0] = ai; l2[1] = b; i2_[1] = bi; }
#pragma unroll
        for (int j = 2; j < TOPK; j++) { l2[j] = NEG_INF; i2_[j] = IDX_MAX; }
        warp_top8_merge(l2, i2_, g_blk_topv[row][blk], g_blk_topi[row][blk]);

        if (lane == 0) {
            float S = 0.f;
#pragma unroll
            for (int w = 0; w < 8; w++) S += sm_s[w];
            g_blk_s[row][blk] = S;
        }
    }

    // ---- last-block-finishes-the-reduction ----
    __threadfence();
    __shared__ int s_ticket;
    __syncthreads();
    if (t == 0) s_ticket = atomicAdd(&g_ctr, 1);
    __syncthreads();
    if (s_ticket != N_BLOCKS - 1) return;
    __threadfence();

    // ---- final merge + selection (one block, 256 threads) ----
    __shared__ float s_topv[BEAM][TOPK];
    __shared__ int   s_topi[BEAM][TOPK];
    __shared__ float s_lse[BEAM];
    __shared__ int   s_beam[BEAM], s_tok[BEAM];
    __shared__ float s_prob[BEAM];

    // warp r: merge row r's 16 block-lists (lane b holds block b's sorted 8)
    {
        const int r = wid;
        float mv[TOPK]; int mi[TOPK];
#pragma unroll
        for (int j = 0; j < TOPK; j++) {
            if (lane < BLKS_PER_ROW) { mv[j] = g_blk_topv[r][lane][j]; mi[j] = g_blk_topi[r][lane][j]; }
            else                     { mv[j] = NEG_INF;                mi[j] = IDX_MAX; }
        }
        warp_top8_merge(mv, mi, s_topv[r], s_topi[r]);

        float S = (lane < BLKS_PER_ROW) ? g_blk_s[r][lane] : 0.f;
        for (int off = 16; off; off >>= 1)
            S += __shfl_xor_sync(F, S, off);
        if (lane == 0) s_lse[r] = logf(S);
    }
    __syncthreads();

    // warp 0: beam top-8 over 64 candidates (tie -> smaller flat index)
    if (wid == 0) {
        const int f0 = lane, f1 = lane + 32;
        float v0 = s_topv[f0 >> 3][f0 & 7] - s_lse[f0 >> 3] + prev[f0 >> 3];
        float v1 = s_topv[f1 >> 3][f1 & 7] - s_lse[f1 >> 3] + prev[f1 >> 3];
        float c0v, c1v; int c0i, c1i;
        if (v1 > v0) { c0v = v1; c0i = f1; c1v = v0; c1i = f0; }
        else         { c0v = v0; c0i = f0; c1v = v1; c1i = f1; }

        int ptr = 0;
#pragma unroll
        for (int r = 0; r < BEAM; r++) {
            float rv; int ri;
            if      (ptr == 0) { rv = c0v; ri = c0i; }
            else if (ptr == 1) { rv = c1v; ri = c1i; }
            else               { rv = NEG_INF; ri = IDX_MAX; }
            int rl = lane;
            for (int off = 16; off; off >>= 1) {
                float ov = __shfl_xor_sync(F, rv, off);
                int   oi = __shfl_xor_sync(F, ri, off);
                int   ol = __shfl_xor_sync(F, rl, off);
                if (ov > rv || (ov == rv && oi < ri)) { rv = ov; ri = oi; rl = ol; }
            }
            if (lane == rl) ptr++;
            if (lane == 0) {
                const int beam = ri >> 3;
                s_beam[r] = beam;
                s_tok[r]  = s_topi[beam][ri & 7];
                s_prob[r] = rv;
            }
        }
    }
    __syncthreads();

    const size_t OFF = KV_ELEMS;
    for (int e = t; e < BEAM * (HIST + 1); e += 256) {
        const int r = e / (HIST + 1), c = e % (HIST + 1);
        out[OFF + e] = (c < HIST) ? (float)save_id[s_beam[r] * HIST + c]
                                  : (float)s_tok[r];
    }
    if (t < BEAM) {
        out[OFF + 1032 + t] = s_prob[t];         // top_beam_prob (8,1)
        out[OFF + 1040 + t] = (float)s_tok[t];   // tbi (8,1)
        g_beam_index[t] = s_beam[t];
    }
    if (t == 0) {
        out[OFF + 1048] = (float)s_tok[0];       // max_logits_idx (1,1)
        g_ctr = 0;                               // reset for next graph replay
    }
}

// ---------------------------------------------------------------------------
// Kernel 2: kv gather (2 GiB streaming copy at the LTS cap). Beam innermost
// so duplicate-beam reads of the same (layer, chunk) dedup in L2.
// ---------------------------------------------------------------------------
__global__ void __launch_bounds__(256) k_gather(const float4* __restrict__ src,
                                                float4*       __restrict__ dst)
{
    const int b     = blockIdx.x & 7;
    const int chunk = (blockIdx.x >> 3) & 63;
    const int l     = blockIdx.x >> 9;
    const int slab     = (l << 3) | b;
    const int src_slab = (l << 3) | g_beam_index[b];

    const size_t out_base = ((size_t)slab     << SLAB_F4_SHIFT) + ((size_t)chunk << 12);
    const size_t in_base  = ((size_t)src_slab << SLAB_F4_SHIFT) + ((size_t)chunk << 12);

#pragma unroll
    for (int k = 0; k < 16; k++) {
        const int off = threadIdx.x + k * 256;
        dst[out_base + off] = src[in_base + off];
    }
}

// ---------------------------------------------------------------------------
extern "C" void kernel_launch(void* const* d_in, const int* in_sizes, int n_in,
                              void* d_out, int out_size)
{
    const float* kv      = (const float*)d_in[0];
    const float* logits  = (const float*)d_in[1];
    const int*   save_id = (const int*)  d_in[2];
    const float* prev    = (const float*)d_in[3];
    float* out = (float*)d_out;

    k_partial<<<N_BLOCKS, 256>>>(logits, prev, save_id, out);
    k_gather<<<16384, 256>>>((const float4*)kv, (float4*)out);
}

// round 7
// speedup vs baseline: 1.0862x; 1.0862x over previous
#include <cuda_runtime.h>
#include <cstdint>

// Problem constants
#define L_DIM   32
#define BEAM    8
#define KV2     2
#define HEADS   8
#define SEQ     1024
#define HDIM    64
#define VOCAB   50257
#define HIST    128
#define TOPK    8

#define KV_ELEMS      268435456ULL     // 32*8*2*8*1024*64
#define SLAB_F4_SHIFT 18               // 262,144 float4 per (layer,beam) slab

#define BLKS_PER_ROW  16
#define BLOCK_ELEMS   3142             // 16*3142 = 50272 >= 50257

#define NEG_INF (__int_as_float(0xff800000))
#define IDX_MAX 0x7fffffff

// cross-kernel scratch
__device__ float g_blk_s[BEAM][BLKS_PER_ROW];
__device__ float g_blk_topv[BEAM][BLKS_PER_ROW][TOPK];
__device__ int   g_blk_topi[BEAM][BLKS_PER_ROW][TOPK];
__device__ int   g_beam_index[BEAM];

// sorted-descending insert, static indices only (registers)
__device__ __forceinline__ void top8_insert(float v, int idx, float lv[TOPK], int li[TOPK])
{
    if (v > lv[TOPK - 1] || (v == lv[TOPK - 1] && idx < li[TOPK - 1])) {
        float cv = v; int ci = idx;
#pragma unroll
        for (int j = 0; j < TOPK; j++) {
            bool gt = (cv > lv[j]) || (cv == lv[j] && ci < li[j]);
            float tv = lv[j]; int ti = li[j];
            if (gt) { lv[j] = cv; li[j] = ci; cv = tv; ci = ti; }
        }
    }
}

// full-warp argmax-remove over per-lane sorted lists -> 8 winners
// (desc, tie: smaller index). All lanes converge; lane 0 stores.
__device__ __forceinline__ void warp_top8_merge(float lv[TOPK], int li[TOPK],
                                                float* out_v, int* out_i)
{
    const unsigned F = 0xffffffffu;
    const int lane = threadIdx.x & 31;
    int ptr = 0;
#pragma unroll
    for (int r = 0; r < TOPK; r++) {
        float rv = NEG_INF; int ri = IDX_MAX;
#pragma unroll
        for (int j = 0; j < TOPK; j++)
            if (j == ptr) { rv = lv[j]; ri = li[j]; }
        int rl = lane;
        for (int off = 16; off; off >>= 1) {
            float ov = __shfl_xor_sync(F, rv, off);
            int   oi = __shfl_xor_sync(F, ri, off);
            int   ol = __shfl_xor_sync(F, rl, off);
            if (ov > rv || (ov == rv && oi < ri)) { rv = ov; ri = oi; rl = ol; }
        }
        if (lane == rl) ptr++;
        if (lane == 0) { out_v[r] = rv; out_i[r] = ri; }
    }
}

// ---------------------------------------------------------------------------
// Kernel 1: partial exp-sum + partial top-8. grid = 8 rows x 16 blocks, 256 thr.
// ---------------------------------------------------------------------------
__global__ void __launch_bounds__(256) k_partial(const float* __restrict__ logits)
{
    const int row = blockIdx.x >> 4;
    const int blk = blockIdx.x & 15;
    const int t   = threadIdx.x;
    const int wid = t >> 5, lane = t & 31;
    const unsigned F = 0xffffffffu;
    const float* __restrict__ x = logits + (size_t)row * VOCAB;

    const int base = blk * BLOCK_ELEMS;
    const int end  = min(base + BLOCK_ELEMS, VOCAB);

    // direct exp-sum (logits ~ N(0,1): no overflow), 4 independent accumulators
    float s0 = 0.f, s1 = 0.f, s2 = 0.f, s3 = 0.f;
    float lv[TOPK]; int li[TOPK];
#pragma unroll
    for (int j = 0; j < TOPK; j++) { lv[j] = NEG_INF; li[j] = IDX_MAX; }

#pragma unroll 1
    for (int i = base + t; i < end; i += 1024) {
        const int i1 = i + 256, i2 = i + 512, i3 = i + 768;
        float v0 = x[i];
        s0 += __expf(v0);
        top8_insert(v0, i, lv, li);
        if (i1 < end) { float v = x[i1]; s1 += __expf(v); top8_insert(v, i1, lv, li); }
        if (i2 < end) { float v = x[i2]; s2 += __expf(v); top8_insert(v, i2, lv, li); }
        if (i3 < end) { float v = x[i3]; s3 += __expf(v); top8_insert(v, i3, lv, li); }
    }

    float s = (s0 + s1) + (s2 + s3);
    for (int off = 16; off; off >>= 1)
        s += __shfl_xor_sync(F, s, off);

    __shared__ float sm_s[8];
    __shared__ float s_wv[8][TOPK];
    __shared__ int   s_wi[8][TOPK];
    if (lane == 0) sm_s[wid] = s;
    warp_top8_merge(lv, li, s_wv[wid], s_wi[wid]);
    __syncthreads();

    // warp 0: merge 8 warps x 8 -> block top-8; sum warp partials
    if (wid == 0) {
        float l2[TOPK]; int i2_[TOPK];
        const int f0 = lane, f1 = lane + 32;
        float a = s_wv[f0 >> 3][f0 & 7]; int ai = s_wi[f0 >> 3][f0 & 7];
        float b = s_wv[f1 >> 3][f1 & 7]; int bi = s_wi[f1 >> 3][f1 & 7];
        if (b > a || (b == a && bi < ai)) { l2[0] = b; i2_[0] = bi; l2[1] = a; i2_[1] = ai; }
        else                              { l2[0] = a; i2_[0] = ai; l2[1] = b; i2_[1] = bi; }
#pragma unroll
        for (int j = 2; j < TOPK; j++) { l2[j] = NEG_INF; i2_[j] = IDX_MAX; }
        warp_top8_merge(l2, i2_, g_blk_topv[row][blk], g_blk_topi[row][blk]);

        if (lane == 0) {
            float S = 0.f;
#pragma unroll
            for (int w = 0; w < 8; w++) S += sm_s[w];
            g_blk_s[row][blk] = S;
        }
    }
}

// ---------------------------------------------------------------------------
// Kernel 2: per-row merge of 16 block-lists + LSE + beam selection + outputs.
// 1 block, 256 threads.
// ---------------------------------------------------------------------------
__global__ void __launch_bounds__(256) k_merge_select(const float* __restrict__ prev,
                                                      const int*   __restrict__ save_id,
                                                      float*       __restrict__ out)
{
    const int t = threadIdx.x;
    const int wid = t >> 5, lane = t & 31;
    const unsigned F = 0xffffffffu;

    __shared__ float s_topv[BEAM][TOPK];
    __shared__ int   s_topi[BEAM][TOPK];
    __shared__ float s_lse[BEAM];
    __shared__ int   s_beam[BEAM], s_tok[BEAM];
    __shared__ float s_prob[BEAM];

    // warp r: merge row r's 16 block-lists (lane b holds block b's sorted 8)
    {
        const int r = wid;
        float mv[TOPK]; int mi[TOPK];
#pragma unroll
        for (int j = 0; j < TOPK; j++) {
            if (lane < BLKS_PER_ROW) { mv[j] = g_blk_topv[r][lane][j]; mi[j] = g_blk_topi[r][lane][j]; }
            else                     { mv[j] = NEG_INF;                mi[j] = IDX_MAX; }
        }
        warp_top8_merge(mv, mi, s_topv[r], s_topi[r]);

        float S = (lane < BLKS_PER_ROW) ? g_blk_s[r][lane] : 0.f;
        for (int off = 16; off; off >>= 1)
            S += __shfl_xor_sync(F, S, off);
        if (lane == 0) s_lse[r] = logf(S);
    }
    __syncthreads();

    // warp 0: beam top-8 over 64 candidates (tie -> smaller flat index)
    if (wid == 0) {
        const int f0 = lane, f1 = lane + 32;
        float v0 = s_topv[f0 >> 3][f0 & 7] - s_lse[f0 >> 3] + prev[f0 >> 3];
        float v1 = s_topv[f1 >> 3][f1 & 7] - s_lse[f1 >> 3] + prev[f1 >> 3];
        float c0v, c1v; int c0i, c1i;
        if (v1 > v0) { c0v = v1; c0i = f1; c1v = v0; c1i = f0; }
        else         { c0v = v0; c0i = f0; c1v = v1; c1i = f1; }

        int ptr = 0;
#pragma unroll
        for (int r = 0; r < BEAM; r++) {
            float rv; int ri;
            if      (ptr == 0) { rv = c0v; ri = c0i; }
            else if (ptr == 1) { rv = c1v; ri = c1i; }
            else               { rv = NEG_INF; ri = IDX_MAX; }
            int rl = lane;
            for (int off = 16; off; off >>= 1) {
                float ov = __shfl_xor_sync(F, rv, off);
                int   oi = __shfl_xor_sync(F, ri, off);
                int   ol = __shfl_xor_sync(F, rl, off);
                if (ov > rv || (ov == rv && oi < ri)) { rv = ov; ri = oi; rl = ol; }
            }
            if (lane == rl) ptr++;
            if (lane == 0) {
                const int beam = ri >> 3;
                s_beam[r] = beam;
                s_tok[r]  = s_topi[beam][ri & 7];
                s_prob[r] = rv;
            }
        }
    }
    __syncthreads();

    const size_t OFF = KV_ELEMS;
    for (int e = t; e < BEAM * (HIST + 1); e += 256) {
        const int r = e / (HIST + 1), c = e % (HIST + 1);
        out[OFF + e] = (c < HIST) ? (float)save_id[s_beam[r] * HIST + c]
                                  : (float)s_tok[r];
    }
    if (t < BEAM) {
        out[OFF + 1032 + t] = s_prob[t];         // top_beam_prob (8,1)
        out[OFF + 1040 + t] = (float)s_tok[t];   // tbi (8,1)
        g_beam_index[t] = s_beam[t];
    }
    if (t == 0)
        out[OFF + 1048] = (float)s_tok[0];       // max_logits_idx (1,1)
}

// ---------------------------------------------------------------------------
// Kernel 3: SOURCE-centric kv gather. Block = (l, chunk, src_beam).
// Loads its 16KB chunk once, fans out to every dst beam whose beam_index
// matches. Unused source beams exit immediately. Every byte is touched
// exactly once chip-wide -> evict-first hints on both sides.
// ---------------------------------------------------------------------------
__global__ void __launch_bounds__(256) k_gather(const float4* __restrict__ src,
                                                float4*       __restrict__ dst)
{
    const int sb    = blockIdx.x & 7;          // source beam (innermost)
    const int chunk = (blockIdx.x >> 3) & 63;
    const int l     = blockIdx.x >> 9;

    __shared__ int s_bi[BEAM];
    if (threadIdx.x < BEAM) s_bi[threadIdx.x] = g_beam_index[threadIdx.x];
    __syncthreads();

    unsigned mask = 0;
#pragma unroll
    for (int b = 0; b < BEAM; b++)
        if (s_bi[b] == sb) mask |= (1u << b);
    if (mask == 0) return;

    const size_t in_base = ((size_t)((l << 3) | sb) << SLAB_F4_SHIFT)
                         + ((size_t)chunk << 12);
    const size_t lbase   = ((size_t)(l << 3) << SLAB_F4_SHIFT)
                         + ((size_t)chunk << 12);

#pragma unroll
    for (int g = 0; g < 4; g++) {
        float4 v[4];
#pragma unroll
        for (int k = 0; k < 4; k++)
            v[k] = __ldcs(&src[in_base + threadIdx.x + (g * 4 + k) * 256]);
#pragma unroll
        for (int b = 0; b < BEAM; b++) {
            if (mask & (1u << b)) {
                const size_t out_base = lbase + ((size_t)b << SLAB_F4_SHIFT);
#pragma unroll
                for (int k = 0; k < 4; k++)
                    __stcs(&dst[out_base + threadIdx.x + (g * 4 + k) * 256], v[k]);
            }
        }
    }
}

// ---------------------------------------------------------------------------
extern "C" void kernel_launch(void* const* d_in, const int* in_sizes, int n_in,
                              void* d_out, int out_size)
{
    const float* kv      = (const float*)d_in[0];
    const float* logits  = (const float*)d_in[1];
    const int*   save_id = (const int*)  d_in[2];
    const float* prev    = (const float*)d_in[3];
    float* out = (float*)d_out;

    k_partial<<<BEAM * BLKS_PER_ROW, 256>>>(logits);
    k_merge_select<<<1, 256>>>(prev, save_id, out);
    k_gather<<<16384, 256>>>((const float4*)kv, (float4*)out);
}

// round 11
// speedup vs baseline: 1.1161x; 1.0276x over previous
#include <cuda_runtime.h>
#include <cstdint>

// Problem constants
#define L_DIM   32
#define BEAM    8
#define KV2     2
#define HEADS   8
#define SEQ     1024
#define HDIM    64
#define VOCAB   50257
#define HIST    128
#define TOPK    8

#define KV_ELEMS       268435456ULL    // 32*8*2*8*1024*64
#define SLAB_F_SHIFT   20              // 1,048,576 floats per (layer,beam) slab

#define BLKS_PER_ROW   32
#define BLOCK_ELEMS    1571            // 32*1571 = 50272 >= 50257

#define NEG_INF (__int_as_float(0xff800000))
#define IDX_MAX 0x7fffffff

// cross-kernel scratch
__device__ float g_blk_s[BEAM][BLKS_PER_ROW];
__device__ float g_blk_topv[BEAM][BLKS_PER_ROW][TOPK];
__device__ int   g_blk_topi[BEAM][BLKS_PER_ROW][TOPK];
__device__ int   g_beam_index[BEAM];

// ---------------- 256-bit global ld/st (sm_100+) ----------------
__device__ __forceinline__ void ldg_v8(const float* p, float r[8])
{
    asm volatile("ld.global.nc.v8.f32 {%0,%1,%2,%3,%4,%5,%6,%7}, [%8];"
                 : "=f"(r[0]), "=f"(r[1]), "=f"(r[2]), "=f"(r[3]),
                   "=f"(r[4]), "=f"(r[5]), "=f"(r[6]), "=f"(r[7])
                 : "l"(p));
}
__device__ __forceinline__ void stg_v8(float* p, const float r[8])
{
    asm volatile("st.global.v8.f32 [%0], {%1,%2,%3,%4,%5,%6,%7,%8};"
                 :: "l"(p),
                    "f"(r[0]), "f"(r[1]), "f"(r[2]), "f"(r[3]),
                    "f"(r[4]), "f"(r[5]), "f"(r[6]), "f"(r[7])
                 : "memory");
}

// sorted-descending insert, static indices only (registers)
__device__ __forceinline__ void top8_insert(float v, int idx, float lv[TOPK], int li[TOPK])
{
    if (v > lv[TOPK - 1] || (v == lv[TOPK - 1] && idx < li[TOPK - 1])) {
        float cv = v; int ci = idx;
#pragma unroll
        for (int j = 0; j < TOPK; j++) {
            bool gt = (cv > lv[j]) || (cv == lv[j] && ci < li[j]);
            float tv = lv[j]; int ti = li[j];
            if (gt) { lv[j] = cv; li[j] = ci; cv = tv; ci = ti; }
        }
    }
}

// full-warp argmax-remove over per-lane sorted lists -> 8 winners
// (desc, tie: smaller index). All lanes converge; lane 0 stores.
__device__ __forceinline__ void warp_top8_merge(float lv[TOPK], int li[TOPK],
                                                float* out_v, int* out_i)
{
    const unsigned F = 0xffffffffu;
    const int lane = threadIdx.x & 31;
    int ptr = 0;
#pragma unroll
    for (int r = 0; r < TOPK; r++) {
        float rv = NEG_INF; int ri = IDX_MAX;
#pragma unroll
        for (int j = 0; j < TOPK; j++)
            if (j == ptr) { rv = lv[j]; ri = li[j]; }
        int rl = lane;
        for (int off = 16; off; off >>= 1) {
            float ov = __shfl_xor_sync(F, rv, off);
            int   oi = __shfl_xor_sync(F, ri, off);
            int   ol = __shfl_xor_sync(F, rl, off);
            if (ov > rv || (ov == rv && oi < ri)) { rv = ov; ri = oi; rl = ol; }
        }
        if (lane == rl) ptr++;
        if (lane == 0) { out_v[r] = rv; out_i[r] = ri; }
    }
}

// ---------------------------------------------------------------------------
// Kernel 1: partial exp-sum + partial top-8. grid = 8 rows x 32 blocks, 256 thr.
// ---------------------------------------------------------------------------
__global__ void __launch_bounds__(256) k_partial(const float* __restrict__ logits)
{
    const int row = blockIdx.x >> 5;
    const int blk = blockIdx.x & 31;
    const int t   = threadIdx.x;
    const int wid = t >> 5, lane = t & 31;
    const unsigned F = 0xffffffffu;
    const float* __restrict__ x = logits + (size_t)row * VOCAB;

    const int base = blk * BLOCK_ELEMS;
    const int end  = min(base + BLOCK_ELEMS, VOCAB);

    // direct exp-sum (logits ~ N(0,1): no overflow), 4 independent accumulators
    float s0 = 0.f, s1 = 0.f, s2 = 0.f, s3 = 0.f;
    float lv[TOPK]; int li[TOPK];
#pragma unroll
    for (int j = 0; j < TOPK; j++) { lv[j] = NEG_INF; li[j] = IDX_MAX; }

#pragma unroll 1
    for (int i = base + t; i < end; i += 1024) {
        const int i1 = i + 256, i2 = i + 512, i3 = i + 768;
        float v0 = x[i];
        s0 += __expf(v0);
        top8_insert(v0, i, lv, li);
        if (i1 < end) { float v = x[i1]; s1 += __expf(v); top8_insert(v, i1, lv, li); }
        if (i2 < end) { float v = x[i2]; s2 += __expf(v); top8_insert(v, i2, lv, li); }
        if (i3 < end) { float v = x[i3]; s3 += __expf(v); top8_insert(v, i3, lv, li); }
    }

    float s = (s0 + s1) + (s2 + s3);
    for (int off = 16; off; off >>= 1)
        s += __shfl_xor_sync(F, s, off);

    __shared__ float sm_s[8];
    __shared__ float s_wv[8][TOPK];
    __shared__ int   s_wi[8][TOPK];
    if (lane == 0) sm_s[wid] = s;
    warp_top8_merge(lv, li, s_wv[wid], s_wi[wid]);
    __syncthreads();

    // warp 0: merge 8 warps x 8 -> block top-8; sum warp partials
    if (wid == 0) {
        float l2[TOPK]; int i2_[TOPK];
        const int f0 = lane, f1 = lane + 32;
        float a = s_wv[f0 >> 3][f0 & 7]; int ai = s_wi[f0 >> 3][f0 & 7];
        float b = s_wv[f1 >> 3][f1 & 7]; int bi = s_wi[f1 >> 3][f1 & 7];
        if (b > a || (b == a && bi < ai)) { l2[0] = b; i2_[0] = bi; l2[1] = a; i2_[1] = ai; }
        else                              { l2[0] = a; i2_[0] = ai; l2[1] = b; i2_[1] = bi; }
#pragma unroll
        for (int j = 2; j < TOPK; j++) { l2[j] = NEG_INF; i2_[j] = IDX_MAX; }
        warp_top8_merge(l2, i2_, g_blk_topv[row][blk], g_blk_topi[row][blk]);

        if (lane == 0) {
            float S = 0.f;
#pragma unroll
            for (int w = 0; w < 8; w++) S += sm_s[w];
            g_blk_s[row][blk] = S;
        }
    }
}

// ---------------------------------------------------------------------------
// Kernel 2: per-row merge of 32 block-lists + LSE + beam selection + outputs.
// 1 block, 256 threads.
// ---------------------------------------------------------------------------
__global__ void __launch_bounds__(256) k_merge_select(const float* __restrict__ prev,
                                                      const int*   __restrict__ save_id,
                                                      float*       __restrict__ out)
{
    const int t = threadIdx.x;
    const int wid = t >> 5, lane = t & 31;
    const unsigned F = 0xffffffffu;

    __shared__ float s_topv[BEAM][TOPK];
    __shared__ int   s_topi[BEAM][TOPK];
    __shared__ float s_lse[BEAM];
    __shared__ int   s_beam[BEAM], s_tok[BEAM];
    __shared__ float s_prob[BEAM];

    // warp r: merge row r's 32 block-lists (lane b holds block b's sorted 8)
    {
        const int r = wid;
        float mv[TOPK]; int mi[TOPK];
#pragma unroll
        for (int j = 0; j < TOPK; j++) {
            mv[j] = g_blk_topv[r][lane][j];
            mi[j] = g_blk_topi[r][lane][j];
        }
        warp_top8_merge(mv, mi, s_topv[r], s_topi[r]);

        float S = g_blk_s[r][lane];
        for (int off = 16; off; off >>= 1)
            S += __shfl_xor_sync(F, S, off);
        if (lane == 0) s_lse[r] = logf(S);
    }
    __syncthreads();

    // warp 0: beam top-8 over 64 candidates (tie -> smaller flat index)
    if (wid == 0) {
        const int f0 = lane, f1 = lane + 32;
        float v0 = s_topv[f0 >> 3][f0 & 7] - s_lse[f0 >> 3] + prev[f0 >> 3];
        float v1 = s_topv[f1 >> 3][f1 & 7] - s_lse[f1 >> 3] + prev[f1 >> 3];
        float c0v, c1v; int c0i, c1i;
        if (v1 > v0) { c0v = v1; c0i = f1; c1v = v0; c1i = f0; }
        else         { c0v = v0; c0i = f0; c1v = v1; c1i = f1; }

        int ptr = 0;
#pragma unroll
        for (int r = 0; r < BEAM; r++) {
            float rv; int ri;
            if      (ptr == 0) { rv = c0v; ri = c0i; }
            else if (ptr == 1) { rv = c1v; ri = c1i; }
            else               { rv = NEG_INF; ri = IDX_MAX; }
            int rl = lane;
            for (int off = 16; off; off >>= 1) {
                float ov = __shfl_xor_sync(F, rv, off);
                int   oi = __shfl_xor_sync(F, ri, off);
                int   ol = __shfl_xor_sync(F, rl, off);
                if (ov > rv || (ov == rv && oi < ri)) { rv = ov; ri = oi; rl = ol; }
            }
            if (lane == rl) ptr++;
            if (lane == 0) {
                const int beam = ri >> 3;
                s_beam[r] = beam;
                s_tok[r]  = s_topi[beam][ri & 7];
                s_prob[r] = rv;
            }
        }
    }
    __syncthreads();

    const size_t OFF = KV_ELEMS;
    for (int e = t; e < BEAM * (HIST + 1); e += 256) {
        const int r = e / (HIST + 1), c = e % (HIST + 1);
        out[OFF + e] = (c < HIST) ? (float)save_id[s_beam[r] * HIST + c]
                                  : (float)s_tok[r];
    }
    if (t < BEAM) {
        out[OFF + 1032 + t] = s_prob[t];         // top_beam_prob (8,1)
        out[OFF + 1040 + t] = (float)s_tok[t];   // tbi (8,1)
        g_beam_index[t] = s_beam[t];
    }
    if (t == 0)
        out[OFF + 1048] = (float)s_tok[0];       // max_logits_idx (1,1)
}

// ---------------------------------------------------------------------------
// Kernel 3: kv gather, dest-centric, beam-innermost (L2 dedups duplicate-beam
// reads), 256-bit ld/st to halve L1 wavefront count. Block = 64KB chunk;
// 256 threads x 8 x 32B = 64KB.
// ---------------------------------------------------------------------------
__global__ void __launch_bounds__(256) k_gather(const float* __restrict__ src,
                                                float*       __restrict__ dst)
{
    const int b     = blockIdx.x & 7;
    const int chunk = (blockIdx.x >> 3) & 63;
    const int l     = blockIdx.x >> 9;
    const int slab     = (l << 3) | b;
    const int src_slab = (l << 3) | g_beam_index[b];

    const size_t out_base = ((size_t)slab     << SLAB_F_SHIFT)
                          + ((size_t)chunk << 14) + threadIdx.x * 8;
    const size_t in_base  = ((size_t)src_slab << SLAB_F_SHIFT)
                          + ((size_t)chunk << 14) + threadIdx.x * 8;

#pragma unroll
    for (int g = 0; g < 2; g++) {
        float r[4][8];
#pragma unroll
        for (int k = 0; k < 4; k++)
            ldg_v8(src + in_base + (g * 4 + k) * 2048, r[k]);
#pragma unroll
        for (int k = 0; k < 4; k++)
            stg_v8(dst + out_base + (g * 4 + k) * 2048, r[k]);
    }
}

// ---------------------------------------------------------------------------
extern "C" void kernel_launch(void* const* d_in, const int* in_sizes, int n_in,
                              void* d_out, int out_size)
{
    const float* kv      = (const float*)d_in[0];
    const float* logits  = (const float*)d_in[1];
    const int*   save_id = (const int*)  d_in[2];
    const float* prev    = (const float*)d_in[3];
    float* out = (float*)d_out;

    k_partial<<<BEAM * BLKS_PER_ROW, 256>>>(logits);
    k_merge_select<<<1, 256>>>(prev, save_id, out);
    k_gather<<<16384, 256>>>(kv, out);
}

// round 13
// speedup vs baseline: 1.1290x; 1.0115x over previous
#include <cuda_runtime.h>
#include <cstdint>

// Problem constants
#define L_DIM   32
#define BEAM    8
#define KV2     2
#define HEADS   8
#define SEQ     1024
#define HDIM    64
#define VOCAB   50257
#define HIST    128
#define TOPK    8

#define KV_ELEMS       268435456ULL    // 32*8*2*8*1024*64 floats
#define SLAB_BYTES     4194304ULL      // bytes per (layer,beam) slab = 1,048,576 floats

#define CHUNK_BYTES    32768           // one bulk-copy unit
#define CHUNKS_PER_SLAB 128            // 4MB / 32KB

#define BLKS_PER_ROW   32
#define BLOCK_ELEMS    1571            // 32*1571 = 50272 >= 50257

#define NEG_INF (__int_as_float(0xff800000))
#define IDX_MAX 0x7fffffff

// cross-kernel scratch
__device__ float g_blk_s[BEAM][BLKS_PER_ROW];
__device__ float g_blk_topv[BEAM][BLKS_PER_ROW][TOPK];
__device__ int   g_blk_topi[BEAM][BLKS_PER_ROW][TOPK];
__device__ int   g_beam_index[BEAM];

// sorted-descending insert, static indices only (registers)
__device__ __forceinline__ void top8_insert(float v, int idx, float lv[TOPK], int li[TOPK])
{
    if (v > lv[TOPK - 1] || (v == lv[TOPK - 1] && idx < li[TOPK - 1])) {
        float cv = v; int ci = idx;
#pragma unroll
        for (int j = 0; j < TOPK; j++) {
            bool gt = (cv > lv[j]) || (cv == lv[j] && ci < li[j]);
            float tv = lv[j]; int ti = li[j];
            if (gt) { lv[j] = cv; li[j] = ci; cv = tv; ci = ti; }
        }
    }
}

// full-warp argmax-remove over per-lane sorted lists -> 8 winners
// (desc, tie: smaller index). All lanes converge; lane 0 stores.
__device__ __forceinline__ void warp_top8_merge(float lv[TOPK], int li[TOPK],
                                                float* out_v, int* out_i)
{
    const unsigned F = 0xffffffffu;
    const int lane = threadIdx.x & 31;
    int ptr = 0;
#pragma unroll
    for (int r = 0; r < TOPK; r++) {
        float rv = NEG_INF; int ri = IDX_MAX;
#pragma unroll
        for (int j = 0; j < TOPK; j++)
            if (j == ptr) { rv = lv[j]; ri = li[j]; }
        int rl = lane;
        for (int off = 16; off; off >>= 1) {
            float ov = __shfl_xor_sync(F, rv, off);
            int   oi = __shfl_xor_sync(F, ri, off);
            int   ol = __shfl_xor_sync(F, rl, off);
            if (ov > rv || (ov == rv && oi < ri)) { rv = ov; ri = oi; rl = ol; }
        }
        if (lane == rl) ptr++;
        if (lane == 0) { out_v[r] = rv; out_i[r] = ri; }
    }
}

// ---------------------------------------------------------------------------
// Kernel 1: partial exp-sum + partial top-8. grid = 8 rows x 32 blocks, 256 thr.
// ---------------------------------------------------------------------------
__global__ void __launch_bounds__(256) k_partial(const float* __restrict__ logits)
{
    const int row = blockIdx.x >> 5;
    const int blk = blockIdx.x & 31;
    const int t   = threadIdx.x;
    const int wid = t >> 5, lane = t & 31;
    const unsigned F = 0xffffffffu;
    const float* __restrict__ x = logits + (size_t)row * VOCAB;

    const int base = blk * BLOCK_ELEMS;
    const int end  = min(base + BLOCK_ELEMS, VOCAB);

    float s0 = 0.f, s1 = 0.f, s2 = 0.f, s3 = 0.f;
    float lv[TOPK]; int li[TOPK];
#pragma unroll
    for (int j = 0; j < TOPK; j++) { lv[j] = NEG_INF; li[j] = IDX_MAX; }

#pragma unroll 1
    for (int i = base + t; i < end; i += 1024) {
        const int i1 = i + 256, i2 = i + 512, i3 = i + 768;
        float v0 = x[i];
        s0 += __expf(v0);
        top8_insert(v0, i, lv, li);
        if (i1 < end) { float v = x[i1]; s1 += __expf(v); top8_insert(v, i1, lv, li); }
        if (i2 < end) { float v = x[i2]; s2 += __expf(v); top8_insert(v, i2, lv, li); }
        if (i3 < end) { float v = x[i3]; s3 += __expf(v); top8_insert(v, i3, lv, li); }
    }

    float s = (s0 + s1) + (s2 + s3);
    for (int off = 16; off; off >>= 1)
        s += __shfl_xor_sync(F, s, off);

    __shared__ float sm_s[8];
    __shared__ float s_wv[8][TOPK];
    __shared__ int   s_wi[8][TOPK];
    if (lane == 0) sm_s[wid] = s;
    warp_top8_merge(lv, li, s_wv[wid], s_wi[wid]);
    __syncthreads();

    if (wid == 0) {
        float l2[TOPK]; int i2_[TOPK];
        const int f0 = lane, f1 = lane + 32;
        float a = s_wv[f0 >> 3][f0 & 7]; int ai = s_wi[f0 >> 3][f0 & 7];
        float b = s_wv[f1 >> 3][f1 & 7]; int bi = s_wi[f1 >> 3][f1 & 7];
        if (b > a || (b == a && bi < ai)) { l2[0] = b; i2_[0] = bi; l2[1] = a; i2_[1] = ai; }
        else                              { l2[0] = a; i2_[0] = ai; l2[1] = b; i2_[1] = bi; }
#pragma unroll
        for (int j = 2; j < TOPK; j++) { l2[j] = NEG_INF; i2_[j] = IDX_MAX; }
        warp_top8_merge(l2, i2_, g_blk_topv[row][blk], g_blk_topi[row][blk]);

        if (lane == 0) {
            float S = 0.f;
#pragma unroll
            for (int w = 0; w < 8; w++) S += sm_s[w];
            g_blk_s[row][blk] = S;
        }
    }
}

// ---------------------------------------------------------------------------
// Kernel 2: per-row merge of 32 block-lists + LSE + beam selection + outputs.
// 1 block, 256 threads.
// ---------------------------------------------------------------------------
__global__ void __launch_bounds__(256) k_merge_select(const float* __restrict__ prev,
                                                      const int*   __restrict__ save_id,
                                                      float*       __restrict__ out)
{
    const int t = threadIdx.x;
    const int wid = t >> 5, lane = t & 31;
    const unsigned F = 0xffffffffu;

    __shared__ float s_topv[BEAM][TOPK];
    __shared__ int   s_topi[BEAM][TOPK];
    __shared__ float s_lse[BEAM];
    __shared__ int   s_beam[BEAM], s_tok[BEAM];
    __shared__ float s_prob[BEAM];

    {
        const int r = wid;
        float mv[TOPK]; int mi[TOPK];
#pragma unroll
        for (int j = 0; j < TOPK; j++) {
            mv[j] = g_blk_topv[r][lane][j];
            mi[j] = g_blk_topi[r][lane][j];
        }
        warp_top8_merge(mv, mi, s_topv[r], s_topi[r]);

        float S = g_blk_s[r][lane];
        for (int off = 16; off; off >>= 1)
            S += __shfl_xor_sync(F, S, off);
        if (lane == 0) s_lse[r] = logf(S);
    }
    __syncthreads();

    if (wid == 0) {
        const int f0 = lane, f1 = lane + 32;
        float v0 = s_topv[f0 >> 3][f0 & 7] - s_lse[f0 >> 3] + prev[f0 >> 3];
        float v1 = s_topv[f1 >> 3][f1 & 7] - s_lse[f1 >> 3] + prev[f1 >> 3];
        float c0v, c1v; int c0i, c1i;
        if (v1 > v0) { c0v = v1; c0i = f1; c1v = v0; c1i = f0; }
        else         { c0v = v0; c0i = f0; c1v = v1; c1i = f1; }

        int ptr = 0;
#pragma unroll
        for (int r = 0; r < BEAM; r++) {
            float rv; int ri;
            if      (ptr == 0) { rv = c0v; ri = c0i; }
            else if (ptr == 1) { rv = c1v; ri = c1i; }
            else               { rv = NEG_INF; ri = IDX_MAX; }
            int rl = lane;
            for (int off = 16; off; off >>= 1) {
                float ov = __shfl_xor_sync(F, rv, off);
                int   oi = __shfl_xor_sync(F, ri, off);
                int   ol = __shfl_xor_sync(F, rl, off);
                if (ov > rv || (ov == rv && oi < ri)) { rv = ov; ri = oi; rl = ol; }
            }
            if (lane == rl) ptr++;
            if (lane == 0) {
                const int beam = ri >> 3;
                s_beam[r] = beam;
                s_tok[r]  = s_topi[beam][ri & 7];
                s_prob[r] = rv;
            }
        }
    }
    __syncthreads();

    const size_t OFF = KV_ELEMS;
    for (int e = t; e < BEAM * (HIST + 1); e += 256) {
        const int r = e / (HIST + 1), c = e % (HIST + 1);
        out[OFF + e] = (c < HIST) ? (float)save_id[s_beam[r] * HIST + c]
                                  : (float)s_tok[r];
    }
    if (t < BEAM) {
        out[OFF + 1032 + t] = s_prob[t];         // top_beam_prob (8,1)
        out[OFF + 1040 + t] = (float)s_tok[t];   // tbi (8,1)
        g_beam_index[t] = s_beam[t];
    }
    if (t == 0)
        out[OFF + 1048] = (float)s_tok[0];       // max_logits_idx (1,1)
}

// ---------------------------------------------------------------------------
// Kernel 3: TMA-bulk source-centric gather.
// CTA = (layer, 32KB chunk, src_beam). If any dst beam maps to src_beam:
// one cp.async.bulk GMEM->SMEM, then one bulk SMEM->GMEM store per dst beam.
// Unique data is read from L2/DRAM exactly once; no L1 wavefront traffic.
// grid = 32 * 128 * 8 = 32768, block = 32 (thread 0 drives the TMA).
// ---------------------------------------------------------------------------
__global__ void __launch_bounds__(32) k_gather_tma(const char* __restrict__ src,
                                                   char*       __restrict__ dst)
{
    __shared__ alignas(128) char buf[CHUNK_BYTES];
    __shared__ alignas(8)  uint64_t mbar;

    const int sb    = blockIdx.x & 7;
    const int chunk = (blockIdx.x >> 3) & (CHUNKS_PER_SLAB - 1);
    const int l     = blockIdx.x >> 10;

    if (threadIdx.x != 0) return;

    // destination mask for this source beam
    unsigned mask = 0;
#pragma unroll
    for (int b = 0; b < BEAM; b++)
        if (g_beam_index[b] == sb) mask |= (1u << b);
    if (mask == 0) return;

    unsigned smem_addr = (unsigned)__cvta_generic_to_shared(buf);
    unsigned mbar_addr = (unsigned)__cvta_generic_to_shared(&mbar);

    // init mbarrier and make it visible to the async proxy
    asm volatile("mbarrier.init.shared.b64 [%0], 1;" :: "r"(mbar_addr) : "memory");
    asm volatile("fence.proxy.async.shared::cta;" ::: "memory");

    const char* gsrc = src + ((size_t)((l << 3) | sb)) * SLAB_BYTES
                           + (size_t)chunk * CHUNK_BYTES;

    asm volatile("mbarrier.arrive.expect_tx.shared.b64 _, [%0], %1;"
                 :: "r"(mbar_addr), "r"((unsigned)CHUNK_BYTES) : "memory");
    asm volatile("cp.async.bulk.shared::cluster.global.mbarrier::complete_tx::bytes "
                 "[%0], [%1], %2, [%3];"
                 :: "r"(smem_addr), "l"(gsrc), "r"((unsigned)CHUNK_BYTES),
                    "r"(mbar_addr) : "memory");

    // wait for load completion (phase 0)
    {
        unsigned done;
        asm volatile(
            "{\n\t.reg .pred p;\n\t"
            "mbarrier.try_wait.parity.shared.b64 p, [%1], 0;\n\t"
            "selp.b32 %0, 1, 0, p;\n\t}"
            : "=r"(done) : "r"(mbar_addr) : "memory");
        while (!done) {
            asm volatile(
                "{\n\t.reg .pred p;\n\t"
                "mbarrier.try_wait.parity.shared.b64 p, [%1], 0, 0x989680;\n\t"
                "selp.b32 %0, 1, 0, p;\n\t}"
                : "=r"(done) : "r"(mbar_addr) : "memory");
        }
    }
    // order SMEM contents for the async-proxy reads below
    asm volatile("fence.proxy.async.shared::cta;" ::: "memory");

    // fan out: one bulk store per destination beam using this source
    const size_t lchunk = (size_t)(l << 3) * SLAB_BYTES + (size_t)chunk * CHUNK_BYTES;
#pragma unroll
    for (int b = 0; b < BEAM; b++) {
        if (mask & (1u << b)) {
            char* gdst = dst + lchunk + (size_t)b * SLAB_BYTES;
            asm volatile("cp.async.bulk.global.shared::cta.bulk_group [%0], [%1], %2;"
                         :: "l"(gdst), "r"(smem_addr), "r"((unsigned)CHUNK_BYTES)
                         : "memory");
        }
    }
    asm volatile("cp.async.bulk.commit_group;" ::: "memory");
    asm volatile("cp.async.bulk.wait_group 0;" ::: "memory");
}

// ---------------------------------------------------------------------------
extern "C" void kernel_launch(void* const* d_in, const int* in_sizes, int n_in,
                              void* d_out, int out_size)
{
    const float* kv      = (const float*)d_in[0];
    const float* logits  = (const float*)d_in[1];
    const int*   save_id = (const int*)  d_in[2];
    const float* prev    = (const float*)d_in[3];
    float* out = (float*)d_out;

    k_partial<<<BEAM * BLKS_PER_ROW, 256>>>(logits);
    k_merge_select<<<1, 256>>>(prev, save_id, out);
    k_gather_tma<<<L_DIM * CHUNKS_PER_SLAB * BEAM, 32>>>((const char*)kv, (char*)out);
}

// round 14
// speedup vs baseline: 1.1532x; 1.0214x over previous
#include <cuda_runtime.h>
#include <cstdint>

// Problem constants
#define L_DIM   32
#define BEAM    8
#define KV2     2
#define HEADS   8
#define SEQ     1024
#define HDIM    64
#define VOCAB   50257
#define HIST    128
#define TOPK    8

#define KV_ELEMS       268435456ULL    // 32*8*2*8*1024*64 floats
#define SLAB_BYTES     4194304ULL      // bytes per (layer,beam) slab

#define CHUNK_BYTES    32768
#define CHUNKS_PER_SLAB 128            // 4MB / 32KB

#define BLKS_PER_ROW   32
#define BLOCK_ELEMS    1571            // 32*1571 = 50272 >= 50257
#define PART_THREADS   512

#define NEG_INF (__int_as_float(0xff800000))
#define IDX_MAX 0x7fffffff

// cross-kernel scratch
__device__ float g_blk_s[BEAM][BLKS_PER_ROW];
__device__ float g_blk_topv[BEAM][BLKS_PER_ROW][TOPK];
__device__ int   g_blk_topi[BEAM][BLKS_PER_ROW][TOPK];
__device__ int   g_beam_index[BEAM];

// sorted-descending insert, static indices only (registers)
__device__ __forceinline__ void top8_insert(float v, int idx, float lv[TOPK], int li[TOPK])
{
    if (v > lv[TOPK - 1] || (v == lv[TOPK - 1] && idx < li[TOPK - 1])) {
        float cv = v; int ci = idx;
#pragma unroll
        for (int j = 0; j < TOPK; j++) {
            bool gt = (cv > lv[j]) || (cv == lv[j] && ci < li[j]);
            float tv = lv[j]; int ti = li[j];
            if (gt) { lv[j] = cv; li[j] = ci; cv = tv; ci = ti; }
        }
    }
}

// compare-swap for (value,index) pairs: keep larger-value (tie: smaller index) first
__device__ __forceinline__ void cswap(float& va, int& ia, float& vb, int& ib)
{
    if (vb > va || (vb == va && ib < ia)) {
        float tv = va; va = vb; vb = tv;
        int   ti = ia; ia = ib; ib = ti;
    }
}

// full-warp argmax-remove over per-lane sorted lists -> 8 winners
// (desc, tie: smaller index). All lanes converge; lane 0 stores.
__device__ __forceinline__ void warp_top8_merge(float lv[TOPK], int li[TOPK],
                                                float* out_v, int* out_i)
{
    const unsigned F = 0xffffffffu;
    const int lane = threadIdx.x & 31;
    int ptr = 0;
#pragma unroll
    for (int r = 0; r < TOPK; r++) {
        float rv = NEG_INF; int ri = IDX_MAX;
#pragma unroll
        for (int j = 0; j < TOPK; j++)
            if (j == ptr) { rv = lv[j]; ri = li[j]; }
        int rl = lane;
        for (int off = 16; off; off >>= 1) {
            float ov = __shfl_xor_sync(F, rv, off);
            int   oi = __shfl_xor_sync(F, ri, off);
            int   ol = __shfl_xor_sync(F, rl, off);
            if (ov > rv || (ov == rv && oi < ri)) { rv = ov; ri = oi; rl = ol; }
        }
        if (lane == rl) ptr++;
        if (lane == 0) { out_v[r] = rv; out_i[r] = ri; }
    }
}

// ---------------------------------------------------------------------------
// Kernel 1: partial exp-sum + partial top-8.
// grid = 8 rows x 32 blocks, 512 threads, ~3 elems/thread (batched loads).
// ---------------------------------------------------------------------------
__global__ void __launch_bounds__(PART_THREADS) k_partial(const float* __restrict__ logits)
{
    const int row = blockIdx.x >> 5;
    const int blk = blockIdx.x & 31;
    const int t   = threadIdx.x;
    const int wid = t >> 5, lane = t & 31;
    const unsigned F = 0xffffffffu;
    const float* __restrict__ x = logits + (size_t)row * VOCAB;

    const int base = blk * BLOCK_ELEMS;
    const int end  = min(base + BLOCK_ELEMS, VOCAB);

    // indices: i0..i2 always valid (min block size 1556 > 1024+512), i3 guarded
    const int i0 = base + t;
    const int i1 = i0 + PART_THREADS;
    const int i2 = i0 + 2 * PART_THREADS;
    const int i3 = i0 + 3 * PART_THREADS;
    const bool h3 = (i3 < end);

    // batched independent loads (MLP), then independent exp accumulators
    float v0 = x[i0];
    float v1 = x[i1];
    float v2 = x[i2];
    float v3 = h3 ? x[i3] : NEG_INF;

    float s = ((__expf(v0) + __expf(v1)) + (__expf(v2) + (h3 ? __expf(v3) : 0.f)));

    float lv[TOPK]; int li[TOPK];
#pragma unroll
    for (int j = 0; j < TOPK; j++) { lv[j] = NEG_INF; li[j] = IDX_MAX; }
    top8_insert(v0, i0, lv, li);
    top8_insert(v1, i1, lv, li);
    top8_insert(v2, i2, lv, li);
    if (h3) top8_insert(v3, i3, lv, li);

    for (int off = 16; off; off >>= 1)
        s += __shfl_xor_sync(F, s, off);

    __shared__ float sm_s[16];
    __shared__ float s_wv[16][TOPK];
    __shared__ int   s_wi[16][TOPK];
    if (lane == 0) sm_s[wid] = s;
    warp_top8_merge(lv, li, s_wv[wid], s_wi[wid]);
    __syncthreads();

    // warp 0: merge 16 warps x 8 = 128 candidates -> block top-8 (4 per lane)
    if (wid == 0) {
        float cv[4]; int ci[4];
#pragma unroll
        for (int k = 0; k < 4; k++) {
            const int f = lane + 32 * k;           // 0..127
            cv[k] = s_wv[f >> 3][f & 7];
            ci[k] = s_wi[f >> 3][f & 7];
        }
        // sort-4 descending (tie: smaller index)
        cswap(cv[0], ci[0], cv[1], ci[1]);
        cswap(cv[2], ci[2], cv[3], ci[3]);
        cswap(cv[0], ci[0], cv[2], ci[2]);
        cswap(cv[1], ci[1], cv[3], ci[3]);
        cswap(cv[1], ci[1], cv[2], ci[2]);

        float l2[TOPK]; int i2_[TOPK];
#pragma unroll
        for (int j = 0; j < TOPK; j++) {
            l2[j]  = (j < 4) ? cv[j] : NEG_INF;
            i2_[j] = (j < 4) ? ci[j] : IDX_MAX;
        }
        warp_top8_merge(l2, i2_, g_blk_topv[row][blk], g_blk_topi[row][blk]);

        if (lane == 0) {
            float S = 0.f;
#pragma unroll
            for (int w = 0; w < 16; w++) S += sm_s[w];
            g_blk_s[row][blk] = S;
        }
    }
}

// ---------------------------------------------------------------------------
// Kernel 2: per-row merge of 32 block-lists + LSE + beam selection + outputs.
// 1 block, 256 threads.
// ---------------------------------------------------------------------------
__global__ void __launch_bounds__(256) k_merge_select(const float* __restrict__ prev,
                                                      const int*   __restrict__ save_id,
                                                      float*       __restrict__ out)
{
    const int t = threadIdx.x;
    const int wid = t >> 5, lane = t & 31;
    const unsigned F = 0xffffffffu;

    __shared__ float s_topv[BEAM][TOPK];
    __shared__ int   s_topi[BEAM][TOPK];
    __shared__ float s_lse[BEAM];
    __shared__ int   s_beam[BEAM], s_tok[BEAM];
    __shared__ float s_prob[BEAM];

    {
        const int r = wid;
        float mv[TOPK]; int mi[TOPK];
#pragma unroll
        for (int j = 0; j < TOPK; j++) {
            mv[j] = g_blk_topv[r][lane][j];
            mi[j] = g_blk_topi[r][lane][j];
        }
        warp_top8_merge(mv, mi, s_topv[r], s_topi[r]);

        float S = g_blk_s[r][lane];
        for (int off = 16; off; off >>= 1)
            S += __shfl_xor_sync(F, S, off);
        if (lane == 0) s_lse[r] = logf(S);
    }
    __syncthreads();

    if (wid == 0) {
        const int f0 = lane, f1 = lane + 32;
        float v0 = s_topv[f0 >> 3][f0 & 7] - s_lse[f0 >> 3] + prev[f0 >> 3];
        float v1 = s_topv[f1 >> 3][f1 & 7] - s_lse[f1 >> 3] + prev[f1 >> 3];
        float c0v, c1v; int c0i, c1i;
        if (v1 > v0) { c0v = v1; c0i = f1; c1v = v0; c1i = f0; }
        else         { c0v = v0; c0i = f0; c1v = v1; c1i = f1; }

        int ptr = 0;
#pragma unroll
        for (int r = 0; r < BEAM; r++) {
            float rv; int ri;
            if      (ptr == 0) { rv = c0v; ri = c0i; }
            else if (ptr == 1) { rv = c1v; ri = c1i; }
            else               { rv = NEG_INF; ri = IDX_MAX; }
            int rl = lane;
            for (int off = 16; off; off >>= 1) {
                float ov = __shfl_xor_sync(F, rv, off);
                int   oi = __shfl_xor_sync(F, ri, off);
                int   ol = __shfl_xor_sync(F, rl, off);
                if (ov > rv || (ov == rv && oi < ri)) { rv = ov; ri = oi; rl = ol; }
            }
            if (lane == rl) ptr++;
            if (lane == 0) {
                const int beam = ri >> 3;
                s_beam[r] = beam;
                s_tok[r]  = s_topi[beam][ri & 7];
                s_prob[r] = rv;
            }
        }
    }
    __syncthreads();

    const size_t OFF = KV_ELEMS;
    for (int e = t; e < BEAM * (HIST + 1); e += 256) {
        const int r = e / (HIST + 1), c = e % (HIST + 1);
        out[OFF + e] = (c < HIST) ? (float)save_id[s_beam[r] * HIST + c]
                                  : (float)s_tok[r];
    }
    if (t < BEAM) {
        out[OFF + 1032 + t] = s_prob[t];         // top_beam_prob (8,1)
        out[OFF + 1040 + t] = (float)s_tok[t];   // tbi (8,1)
        g_beam_index[t] = s_beam[t];
    }
    if (t == 0)
        out[OFF + 1048] = (float)s_tok[0];       // max_logits_idx (1,1)
}

// ---------------------------------------------------------------------------
// Kernel 3: TMA-bulk source-centric gather with L2 evict-first hints.
// CTA = (layer, 32KB chunk, src_beam). One bulk load, fan-out bulk stores.
// ---------------------------------------------------------------------------
__global__ void __launch_bounds__(32) k_gather_tma(const char* __restrict__ src,
                                                   char*       __restrict__ dst)
{
    __shared__ alignas(128) char buf[CHUNK_BYTES];
    __shared__ alignas(8)  uint64_t mbar;

    const int sb    = blockIdx.x & 7;
    const int chunk = (blockIdx.x >> 3) & (CHUNKS_PER_SLAB - 1);
    const int l     = blockIdx.x >> 10;

    if (threadIdx.x != 0) return;

    unsigned mask = 0;
#pragma unroll
    for (int b = 0; b < BEAM; b++)
        if (g_beam_index[b] == sb) mask |= (1u << b);
    if (mask == 0) return;

    unsigned smem_addr = (unsigned)__cvta_generic_to_shared(buf);
    unsigned mbar_addr = (unsigned)__cvta_generic_to_shared(&mbar);

    uint64_t pol;
    asm volatile("createpolicy.fractional.L2::evict_first.b64 %0, 1.0;" : "=l"(pol));

    asm volatile("mbarrier.init.shared.b64 [%0], 1;" :: "r"(mbar_addr) : "memory");
    asm volatile("fence.proxy.async.shared::cta;" ::: "memory");

    const char* gsrc = src + ((size_t)((l << 3) | sb)) * SLAB_BYTES
                           + (size_t)chunk * CHUNK_BYTES;

    asm volatile("mbarrier.arrive.expect_tx.shared.b64 _, [%0], %1;"
                 :: "r"(mbar_addr), "r"((unsigned)CHUNK_BYTES) : "memory");
    asm volatile("cp.async.bulk.shared::cluster.global.mbarrier::complete_tx::bytes.L2::cache_hint "
                 "[%0], [%1], %2, [%3], %4;"
                 :: "r"(smem_addr), "l"(gsrc), "r"((unsigned)CHUNK_BYTES),
                    "r"(mbar_addr), "l"(pol) : "memory");

    // wait for load completion (phase 0)
    {
        unsigned done;
        asm volatile(
            "{\n\t.reg .pred p;\n\t"
            "mbarrier.try_wait.parity.shared.b64 p, [%1], 0;\n\t"
            "selp.b32 %0, 1, 0, p;\n\t}"
            : "=r"(done) : "r"(mbar_addr) : "memory");
        while (!done) {
            asm volatile(
                "{\n\t.reg .pred p;\n\t"
                "mbarrier.try_wait.parity.shared.b64 p, [%1], 0, 0x989680;\n\t"
                "selp.b32 %0, 1, 0, p;\n\t}"
                : "=r"(done) : "r"(mbar_addr) : "memory");
        }
    }
    asm volatile("fence.proxy.async.shared::cta;" ::: "memory");

    const size_t lchunk = (size_t)(l << 3) * SLAB_BYTES + (size_t)chunk * CHUNK_BYTES;
#pragma unroll
    for (int b = 0; b < BEAM; b++) {
        if (mask & (1u << b)) {
            char* gdst = dst + lchunk + (size_t)b * SLAB_BYTES;
            asm volatile("cp.async.bulk.global.shared::cta.bulk_group.L2::cache_hint "
                         "[%0], [%1], %2, %3;"
                         :: "l"(gdst), "r"(smem_addr), "r"((unsigned)CHUNK_BYTES),
                            "l"(pol) : "memory");
        }
    }
    asm volatile("cp.async.bulk.commit_group;" ::: "memory");
    asm volatile("cp.async.bulk.wait_group 0;" ::: "memory");
}

// ---------------------------------------------------------------------------
extern "C" void kernel_launch(void* const* d_in, const int* in_sizes, int n_in,
                              void* d_out, int out_size)
{
    const float* kv      = (const float*)d_in[0];
    const float* logits  = (const float*)d_in[1];
    const int*   save_id = (const int*)  d_in[2];
    const float* prev    = (const float*)d_in[3];
    float* out = (float*)d_out;

    k_partial<<<BEAM * BLKS_PER_ROW, PART_THREADS>>>(logits);
    k_merge_select<<<1, 256>>>(prev, save_id, out);
    k_gather_tma<<<L_DIM * CHUNKS_PER_SLAB * BEAM, 32>>>((const char*)kv, (char*)out);
}

// round 17
// speedup vs baseline: 1.1543x; 1.0009x over previous
#include <cuda_runtime.h>
#include <cstdint>

// Problem constants
#define L_DIM   32
#define BEAM    8
#define KV2     2
#define HEADS   8
#define SEQ     1024
#define HDIM    64
#define VOCAB   50257
#define HIST    128
#define TOPK    8

#define KV_ELEMS       268435456ULL    // 32*8*2*8*1024*64 floats
#define SLAB_BYTES     4194304ULL      // bytes per (layer,beam) slab

#define CHUNK_BYTES    32768
#define CHUNKS_PER_SLAB 128            // 4MB / 32KB

#define BLKS_PER_ROW   32
#define BLOCK_ELEMS    1571            // 32*1571 = 50272 >= 50257
#define PART_THREADS   512

typedef unsigned long long u64k;

// cross-kernel scratch
__device__ float g_blk_s[BEAM][BLKS_PER_ROW];
__device__ u64k  g_blk_key[BEAM][BLKS_PER_ROW][TOPK];
__device__ int   g_beam_index[BEAM];

// ---------------- packed key: (monotone float bits)<<32 | ~idx ----------------
// larger key  <=>  larger value, or equal value with smaller index.
__device__ __forceinline__ u64k pack_key(float v, int idx)
{
    unsigned b = __float_as_uint(v);
    unsigned mono = b ^ ((unsigned)((int)b >> 31) | 0x80000000u);
    return ((u64k)mono << 32) | (unsigned)(~idx);
}
__device__ __forceinline__ float key_val(u64k k)
{
    unsigned mono = (unsigned)(k >> 32);
    unsigned b = (mono & 0x80000000u) ? (mono ^ 0x80000000u) : ~mono;
    return __uint_as_float(b);
}
__device__ __forceinline__ int key_idx(u64k k)
{
    return (int)~(unsigned)k;
}

// descending compare-swap
__device__ __forceinline__ void kswap(u64k& a, u64k& b)
{
    u64k mx = a > b ? a : b;
    u64k mn = a > b ? b : a;
    a = mx; b = mn;
}

// 5-level warp butterfly: each lane enters with its sorted-desc 8-list
// (zero-padded allowed); exits with the warp-wide top-8, sorted desc, in ALL lanes.
// Per level: bitonic half-cleaner of (A, reverse(B)) + 3-level bitonic cleanup.
__device__ __forceinline__ void warp_merge8(u64k k[TOPK])
{
    const unsigned F = 0xffffffffu;
#pragma unroll
    for (int off = 16; off; off >>= 1) {
        u64k o[TOPK];
#pragma unroll
        for (int j = 0; j < TOPK; j++) o[j] = __shfl_xor_sync(F, k[j], off);
        u64k L[TOPK];
#pragma unroll
        for (int j = 0; j < TOPK; j++) {
            u64k a = k[j], b = o[7 - j];
            L[j] = a > b ? a : b;          // half-cleaner: top-8 of union (bitonic)
        }
        kswap(L[0], L[4]); kswap(L[1], L[5]); kswap(L[2], L[6]); kswap(L[3], L[7]);
        kswap(L[0], L[2]); kswap(L[1], L[3]); kswap(L[4], L[6]); kswap(L[5], L[7]);
        kswap(L[0], L[1]); kswap(L[2], L[3]); kswap(L[4], L[5]); kswap(L[6], L[7]);
#pragma unroll
        for (int j = 0; j < TOPK; j++) k[j] = L[j];
    }
}

// ---------------------------------------------------------------------------
// Kernel 1: partial exp-sum + partial top-8.
// grid = 8 rows x 32 blocks, 512 threads, ~3 elems/thread.
// ---------------------------------------------------------------------------
__global__ void __launch_bounds__(PART_THREADS) k_partial(const float* __restrict__ logits)
{
    const int row = blockIdx.x >> 5;
    const int blk = blockIdx.x & 31;
    const int t   = threadIdx.x;
    const int wid = t >> 5, lane = t & 31;
    const unsigned F = 0xffffffffu;
    const float* __restrict__ x = logits + (size_t)row * VOCAB;

    const int base = blk * BLOCK_ELEMS;
    const int end  = min(base + BLOCK_ELEMS, VOCAB);

    const int i0 = base + t;
    const int i1 = i0 + PART_THREADS;
    const int i2 = i0 + 2 * PART_THREADS;
    const int i3 = i0 + 3 * PART_THREADS;
    const bool h3 = (i3 < end);

    // batched loads (i0..i2 always in range: min block payload 1556 > 1536)
    float v0 = x[i0];
    float v1 = x[i1];
    float v2 = x[i2];
    float v3 = h3 ? x[i3] : 0.f;

    float s = (__expf(v0) + __expf(v1)) + (__expf(v2) + (h3 ? __expf(v3) : 0.f));

    // sort-4 network on packed keys, zero-pad to 8
    u64k k0 = pack_key(v0, i0);
    u64k k1 = pack_key(v1, i1);
    u64k k2 = pack_key(v2, i2);
    u64k k3 = h3 ? pack_key(v3, i3) : 0ULL;
    kswap(k0, k1); kswap(k2, k3); kswap(k0, k2); kswap(k1, k3); kswap(k1, k2);

    u64k k[TOPK] = { k0, k1, k2, k3, 0ULL, 0ULL, 0ULL, 0ULL };
    warp_merge8(k);                       // warp top-8 in all lanes

    for (int off = 16; off; off >>= 1)
        s += __shfl_xor_sync(F, s, off);

    __shared__ float sm_s[16];
    __shared__ u64k  s_wk[16][TOPK];
    if (lane == 0) {
        sm_s[wid] = s;
#pragma unroll
        for (int j = 0; j < TOPK; j++) s_wk[wid][j] = k[j];
    }
    __syncthreads();

    // warp 0: merge the 16 warp lists (lane w holds list w; lanes 16-31 empty)
    if (wid == 0) {
        u64k m[TOPK];
#pragma unroll
        for (int j = 0; j < TOPK; j++)
            m[j] = (lane < 16) ? s_wk[lane][j] : 0ULL;
        warp_merge8(m);

        if (lane == 0) {
#pragma unroll
            for (int j = 0; j < TOPK; j++) g_blk_key[row][blk][j] = m[j];
            float S = 0.f;
#pragma unroll
            for (int w = 0; w < 16; w++) S += sm_s[w];
            g_blk_s[row][blk] = S;
        }
    }
}

// ---------------------------------------------------------------------------
// Kernel 2: per-row merge of 32 block-lists + LSE + beam selection + outputs.
// 1 block, 256 threads (8 warps: warp r handles row r, then warp 0 selects).
// ---------------------------------------------------------------------------
__global__ void __launch_bounds__(256) k_merge_select(const float* __restrict__ prev,
                                                      const int*   __restrict__ save_id,
                                                      float*       __restrict__ out)
{
    const int t = threadIdx.x;
    const int wid = t >> 5, lane = t & 31;
    const unsigned F = 0xffffffffu;

    __shared__ u64k  s_key[BEAM][TOPK];   // row top-8 (packed: logit, vocab idx)
    __shared__ float s_lse[BEAM];
    __shared__ int   s_beam[BEAM], s_tok[BEAM];
    __shared__ float s_prob[BEAM];

    // warp r: merge row r's 32 block-lists (lane b holds block b's sorted 8)
    {
        const int r = wid;
        u64k m[TOPK];
#pragma unroll
        for (int j = 0; j < TOPK; j++) m[j] = g_blk_key[r][lane][j];
        warp_merge8(m);

        float S = g_blk_s[r][lane];
        for (int off = 16; off; off >>= 1)
            S += __shfl_xor_sync(F, S, off);
        if (lane == 0) {
            s_lse[r] = logf(S);
#pragma unroll
            for (int j = 0; j < TOPK; j++) s_key[r][j] = m[j];
        }
    }
    __syncthreads();

    // warp 0: beam top-8 over 64 candidates (flat = row*8+slot, tie -> smaller flat)
    if (wid == 0) {
        const int f0 = lane, f1 = lane + 32;
        float v0 = key_val(s_key[f0 >> 3][f0 & 7]) - s_lse[f0 >> 3] + prev[f0 >> 3];
        float v1 = key_val(s_key[f1 >> 3][f1 & 7]) - s_lse[f1 >> 3] + prev[f1 >> 3];
        u64k c0 = pack_key(v0, f0);
        u64k c1 = pack_key(v1, f1);
        kswap(c0, c1);
        u64k k[TOPK] = { c0, c1, 0ULL, 0ULL, 0ULL, 0ULL, 0ULL, 0ULL };
        warp_merge8(k);                   // beam top-8, sorted, in all lanes

        if (lane < BEAM) {
            const u64k kr = k[lane];
            const int flat = key_idx(kr);
            const int beam = flat >> 3;
            const int tok  = key_idx(s_key[beam][flat & 7]);
            s_beam[lane] = beam;
            s_tok[lane]  = tok;
            s_prob[lane] = key_val(kr);
            g_beam_index[lane] = beam;
        }
    }
    __syncthreads();

    const size_t OFF = KV_ELEMS;
    for (int e = t; e < BEAM * (HIST + 1); e += 256) {
        const int r = e / (HIST + 1), c = e % (HIST + 1);
        out[OFF + e] = (c < HIST) ? (float)save_id[s_beam[r] * HIST + c]
                                  : (float)s_tok[r];
    }
    if (t < BEAM) {
        out[OFF + 1032 + t] = s_prob[t];         // top_beam_prob (8,1)
        out[OFF + 1040 + t] = (float)s_tok[t];   // tbi (8,1)
    }
    if (t == 0)
        out[OFF + 1048] = (float)s_tok[0];       // max_logits_idx (1,1)
}

// ---------------------------------------------------------------------------
// Kernel 3: TMA-bulk source-centric gather with L2 evict-first hints.
// CTA = (layer, 32KB chunk, src_beam). One bulk load, fan-out bulk stores.
// (At the DRAM floor — unchanged from R14.)
// ---------------------------------------------------------------------------
__global__ void __launch_bounds__(32) k_gather_tma(const char* __restrict__ src,
                                                   char*       __restrict__ dst)
{
    __shared__ alignas(128) char buf[CHUNK_BYTES];
    __shared__ alignas(8)  uint64_t mbar;

    const int sb    = blockIdx.x & 7;
    const int chunk = (blockIdx.x >> 3) & (CHUNKS_PER_SLAB - 1);
    const int l     = blockIdx.x >> 10;

    if (threadIdx.x != 0) return;

    unsigned mask = 0;
#pragma unroll
    for (int b = 0; b < BEAM; b++)
        if (g_beam_index[b] == sb) mask |= (1u << b);
    if (mask == 0) return;

    unsigned smem_addr = (unsigned)__cvta_generic_to_shared(buf);
    unsigned mbar_addr = (unsigned)__cvta_generic_to_shared(&mbar);

    uint64_t pol;
    asm volatile("createpolicy.fractional.L2::evict_first.b64 %0, 1.0;" : "=l"(pol));

    asm volatile("mbarrier.init.shared.b64 [%0], 1;" :: "r"(mbar_addr) : "memory");
    asm volatile("fence.proxy.async.shared::cta;" ::: "memory");

    const char* gsrc = src + ((size_t)((l << 3) | sb)) * SLAB_BYTES
                           + (size_t)chunk * CHUNK_BYTES;

    asm volatile("mbarrier.arrive.expect_tx.shared.b64 _, [%0], %1;"
                 :: "r"(mbar_addr), "r"((unsigned)CHUNK_BYTES) : "memory");
    asm volatile("cp.async.bulk.shared::cluster.global.mbarrier::complete_tx::bytes.L2::cache_hint "
                 "[%0], [%1], %2, [%3], %4;"
                 :: "r"(smem_addr), "l"(gsrc), "r"((unsigned)CHUNK_BYTES),
                    "r"(mbar_addr), "l"(pol) : "memory");

    // wait for load completion (phase 0)
    {
        unsigned done;
        asm volatile(
            "{\n\t.reg .pred p;\n\t"
            "mbarrier.try_wait.parity.shared.b64 p, [%1], 0;\n\t"
            "selp.b32 %0, 1, 0, p;\n\t}"
            : "=r"(done) : "r"(mbar_addr) : "memory");
        while (!done) {
            asm volatile(
                "{\n\t.reg .pred p;\n\t"
                "mbarrier.try_wait.parity.shared.b64 p, [%1], 0, 0x989680;\n\t"
                "selp.b32 %0, 1, 0, p;\n\t}"
                : "=r"(done) : "r"(mbar_addr) : "memory");
        }
    }
    asm volatile("fence.proxy.async.shared::cta;" ::: "memory");

    const size_t lchunk = (size_t)(l << 3) * SLAB_BYTES + (size_t)chunk * CHUNK_BYTES;
#pragma unroll
    for (int b = 0; b < BEAM; b++) {
        if (mask & (1u << b)) {
            char* gdst = dst + lchunk + (size_t)b * SLAB_BYTES;
            asm volatile("cp.async.bulk.global.shared::cta.bulk_group.L2::cache_hint "
                         "[%0], [%1], %2, %3;"
                         :: "l"(gdst), "r"(smem_addr), "r"((unsigned)CHUNK_BYTES),
                            "l"(pol) : "memory");
        }
    }
    asm volatile("cp.async.bulk.commit_group;" ::: "memory");
    asm volatile("cp.async.bulk.wait_group 0;" ::: "memory");
}

// ---------------------------------------------------------------------------
extern "C" void kernel_launch(void* const* d_in, const int* in_sizes, int n_in,
                              void* d_out, int out_size)
{
    const float* kv      = (const float*)d_in[0];
    const float* logits  = (const float*)d_in[1];
    const int*   save_id = (const int*)  d_in[2];
    const float* prev    = (const float*)d_in[3];
    float* out = (float*)d_out;

    k_partial<<<BEAM * BLKS_PER_ROW, PART_THREADS>>>(logits);
    k_merge_select<<<1, 256>>>(prev, save_id, out);
    k_gather_tma<<<L_DIM * CHUNKS_PER_SLAB * BEAM, 32>>>((const char*)kv, (char*)out);
}